// round 4
// baseline (speedup 1.0000x reference)
#include <cuda_runtime.h>

#define NBATCH 2
#define WW 80
#define NTOK 6400
#define NHEADS 8
#define HD 16
#define ATTN_SCALE 0.25f

// ---------------- scratch (static __device__ — no allocations) ----------------
__device__ float g_Q[(size_t)NBATCH * NHEADS * NTOK * HD];     // (b,h,tok,d)
__device__ float g_K[(size_t)NBATCH * NHEADS * NTOK * HD];
__device__ float g_V[(size_t)NBATCH * NHEADS * NTOK * HD];
__device__ float g_Osum[(size_t)NBATCH * NTOK * 128];          // (b,dest_tok, h*16+d)
__device__ float g_Wc[128 * 128];                              // wproj @ wfinal
__device__ float g_bc[128];                                    // 3*bproj@wfinal + bfinal
__device__ float g_Vc40[64 * 40 * 16];                         // per bh: column sums of V
__device__ float g_Vr40[64 * 40 * 16];                         // per bh: row sums of V

__device__ __forceinline__ void load16(const float* __restrict__ p, float* r) {
#pragma unroll
    for (int i = 0; i < 4; i++) {
        float4 t = ((const float4*)p)[i];
        r[4 * i + 0] = t.x; r[4 * i + 1] = t.y; r[4 * i + 2] = t.z; r[4 * i + 3] = t.w;
    }
}

// ---------------- QKV projection: X(12800,128) @ [wq|wkv](128,384) ----------------
__global__ __launch_bounds__(256) void qkv_gemm_kernel(
    const float* __restrict__ X, const float* __restrict__ wq,
    const float* __restrict__ wkv) {
    __shared__ float As[16][64];
    __shared__ float Bs[16][64];
    const int m0 = blockIdx.x * 64;
    const int n0 = blockIdx.y * 64;
    const float* bsrc; int ld;
    if (n0 < 128) { bsrc = wq + n0; ld = 128; }
    else          { bsrc = wkv + (n0 - 128); ld = 256; }
    const int tid = threadIdx.x;
    const int tm = tid >> 4, tn = tid & 15;
    float acc[4][4];
#pragma unroll
    for (int i = 0; i < 4; i++)
#pragma unroll
        for (int j = 0; j < 4; j++) acc[i][j] = 0.f;

    for (int k0 = 0; k0 < 128; k0 += 16) {
        {
            int row = tid >> 2, kp = (tid & 3) << 2;
            float4 av = *(const float4*)&X[(size_t)(m0 + row) * 128 + k0 + kp];
            As[kp + 0][row] = av.x; As[kp + 1][row] = av.y;
            As[kp + 2][row] = av.z; As[kp + 3][row] = av.w;
            int kk = tid >> 4, j4 = (tid & 15) << 2;
            *(float4*)&Bs[kk][j4] = *(const float4*)&bsrc[(size_t)(k0 + kk) * ld + j4];
        }
        __syncthreads();
#pragma unroll
        for (int kk = 0; kk < 16; kk++) {
            float4 a = *(const float4*)&As[kk][tm << 2];
            float4 bv = *(const float4*)&Bs[kk][tn << 2];
            float aa[4] = {a.x, a.y, a.z, a.w};
            float bb[4] = {bv.x, bv.y, bv.z, bv.w};
#pragma unroll
            for (int i = 0; i < 4; i++)
#pragma unroll
                for (int j = 0; j < 4; j++) acc[i][j] = fmaf(aa[i], bb[j], acc[i][j]);
        }
        __syncthreads();
    }
    const int region = n0 >> 7;                 // 0:Q 1:K 2:V
    float* dst = (region == 0) ? g_Q : (region == 1 ? g_K : g_V);
    const int jb = (n0 & 127) + (tn << 2);
    const int h = jb >> 4, dd = jb & 15;
#pragma unroll
    for (int i = 0; i < 4; i++) {
        int t = m0 + (tm << 2) + i;
        int b = t / NTOK, tok = t - b * NTOK;
        float4 v = make_float4(acc[i][0], acc[i][1], acc[i][2], acc[i][3]);
        *(float4*)&dst[((size_t)(b * NHEADS + h) * NTOK + tok) * HD + dd] = v;
    }
}

// ---------------- Wc = wproj @ wfinal ; bc = 3*bproj@wfinal + bfinal ----------------
__global__ void wc_kernel(const float* __restrict__ wproj, const float* __restrict__ wfinal,
                          const float* __restrict__ bproj, const float* __restrict__ bfinal) {
    int i = blockIdx.x, j = threadIdx.x;
    float s = 0.f;
    for (int k = 0; k < 128; k++) s = fmaf(wproj[i * 128 + k], wfinal[k * 128 + j], s);
    g_Wc[i * 128 + j] = s;
    if (i == 0) {
        float sb = 0.f;
        for (int k = 0; k < 128; k++) sb = fmaf(bproj[k], wfinal[k * 128 + j], sb);
        g_bc[j] = 3.f * sb + bfinal[j];
    }
}

// ---------------- V row/col sums for p=40 rel-pos decomposition ----------------
__global__ void vsum40_kernel() {
    const int bh = blockIdx.x;                  // (b*4 + blk)*8 + h
    const int b = bh >> 5, blk = (bh >> 3) & 3, h = bh & 7;
    const int bi = blk >> 1, bj = blk & 1;
    const int tid = threadIdx.x;                // 640
    const int idx = tid >> 4, dd = tid & 15;
    const float* Vb = g_V + (size_t)(b * NHEADS + h) * NTOK * HD;
    float sc = 0.f, sr = 0.f;
    for (int k2 = 0; k2 < 40; k2++) {
        sc += Vb[((bi * 40 + k2) * WW + bj * 40 + idx) * HD + dd];
        sr += Vb[((bi * 40 + idx) * WW + bj * 40 + k2) * HD + dd];
    }
    g_Vc40[bh * 640 + idx * 16 + dd] = sc;
    g_Vr40[bh * 640 + idx * 16 + dd] = sr;
}

// ---------------- attention for p in {4,8}: whole block resident ----------------
// Reference output is NOT un-patchified — flat reshape, so the destination
// token index is patch-major: (bi*NBW + bj)*P*P + r*P + c.
template <int P, int HPC, bool ACCUM>
__global__ __launch_bounds__(P * P * HPC) void attn_small_kernel(
    const float* __restrict__ relw, const float* __restrict__ relh) {
    constexpr int N = P * P;
    constexpr int THREADS = N * HPC;
    constexpr int NBW = WW / P;
    constexpr int NB = NBW * NBW;
    constexpr int HG = NHEADS / HPC;
    __shared__ float Ks[HPC][N][16];
    __shared__ float Vs[HPC][N][16];
    __shared__ float Vc[HPC][P][16];
    __shared__ float Vr[HPC][P][16];
    __shared__ float rwT[16][2 * P];
    __shared__ float rhT[16][2 * P];

    const int cta = blockIdx.x;
    const int hg = cta % HG;
    const int blk = (cta / HG) % NB;
    const int b = cta / (HG * NB);
    const int bi = blk / NBW, bj = blk % NBW;
    const int tid = threadIdx.x;
    const int hh = tid / N;
    const int qi = tid - hh * N;
    const int h = hg * HPC + hh;

    for (int e = tid; e < (2 * P - 1) * 16; e += THREADS) {
        int rr = e >> 4, d = e & 15;
        rwT[d][rr] = relw[e];
        rhT[d][rr] = relh[e];
    }
    for (int e = tid; e < HPC * N * 4; e += THREADS) {
        int hl = e / (N * 4);
        int rem = e - hl * (N * 4);
        int key = rem >> 2, part = (rem & 3) << 2;
        int kr = key / P, kc = key - kr * P;
        int ktok = (bi * P + kr) * WW + bj * P + kc;
        size_t basek = (size_t)(b * NHEADS + hg * HPC + hl) * NTOK;
        *(float4*)&Ks[hl][key][part] = *(const float4*)&g_K[(basek + ktok) * HD + part];
        *(float4*)&Vs[hl][key][part] = *(const float4*)&g_V[(basek + ktok) * HD + part];
    }
    __syncthreads();
    for (int e = tid; e < HPC * P * 16; e += THREADS) {
        int hl = e / (P * 16);
        int rem = e - hl * (P * 16);
        int idx = rem >> 4, dd = rem & 15;
        float sc = 0.f, sr = 0.f;
#pragma unroll
        for (int k2 = 0; k2 < P; k2++) {
            sc += Vs[hl][k2 * P + idx][dd];
            sr += Vs[hl][idx * P + k2][dd];
        }
        Vc[hl][idx][dd] = sc;
        Vr[hl][idx][dd] = sr;
    }
    __syncthreads();

    const int r = qi / P, c = qi - (qi / P) * P;
    const int qtok = (bi * P + r) * WW + bj * P + c;     // spatial (for reading Q)
    const size_t base = (size_t)(b * NHEADS + h) * NTOK;
    float q[16];
    load16(&g_Q[(base + qtok) * HD], q);
    float o[16];
#pragma unroll
    for (int d = 0; d < 16; d++) o[d] = 0.f;
    float ssum = 0.f;

    for (int kk = 0; kk < N; kk++) {
        float kv[16];
        load16(&Ks[hh][kk][0], kv);
        float s = 0.f;
#pragma unroll
        for (int d = 0; d < 16; d++) s = fmaf(q[d], kv[d], s);
        float ew = __expf(s * ATTN_SCALE);
        ssum += ew;
        float vv[16];
        load16(&Vs[hh][kk][0], vv);
#pragma unroll
        for (int d = 0; d < 16; d++) o[d] = fmaf(ew, vv[d], o[d]);
    }
    float inv = 1.f / ssum;
#pragma unroll
    for (int d = 0; d < 16; d++) o[d] *= inv;

    const int cw = P - 1 - c, rw = P - 1 - r;
#pragma unroll 2
    for (int kc = 0; kc < P; kc++) {
        float w = 0.f, wh = 0.f;
#pragma unroll
        for (int d = 0; d < 16; d++) {
            w = fmaf(q[d], rwT[d][kc + cw], w);
            wh = fmaf(q[d], rhT[d][kc + rw], wh);
        }
        float vcv[16], vrv[16];
        load16(&Vc[hh][kc][0], vcv);
        load16(&Vr[hh][kc][0], vrv);
#pragma unroll
        for (int d = 0; d < 16; d++) {
            o[d] = fmaf(w, vcv[d], o[d]);
            o[d] = fmaf(wh, vrv[d], o[d]);
        }
    }
    // patch-major destination (flat reshape in reference)
    const int dtok = (bi * NBW + bj) * N + qi;
    float* dst = g_Osum + ((size_t)b * NTOK + dtok) * 128 + h * HD;
#pragma unroll
    for (int d4 = 0; d4 < 4; d4++) {
        float4 val = make_float4(o[4 * d4], o[4 * d4 + 1], o[4 * d4 + 2], o[4 * d4 + 3]);
        if (ACCUM) {
            float4 cur = *(float4*)&dst[4 * d4];
            val.x += cur.x; val.y += cur.y; val.z += cur.z; val.w += cur.w;
        }
        *(float4*)&dst[4 * d4] = val;
    }
}

// ---------------- attention for p=40 (n=1600): K/V streamed through smem ----------------
// 2 queries per thread: K/V shared-mem reads amortized over both queries.
// 160 threads/CTA x 2 queries x 5 CTAs = 1600 queries per block-head.
__global__ __launch_bounds__(160) void attn40_kernel(
    const float* __restrict__ relw, const float* __restrict__ relh) {
    __shared__ float Ks[160][16];
    __shared__ float Vs[160][16];
    __shared__ float rwT[16][80];
    __shared__ float rhT[16][80];
    __shared__ float Vc[40][16];
    __shared__ float Vr[40][16];

    const int bh = blockIdx.x / 5;
    const int qc = blockIdx.x - bh * 5;
    const int b = bh >> 5, blk = (bh >> 3) & 3, h = bh & 7;
    const int bi = blk >> 1, bj = blk & 1;
    const int tid = threadIdx.x;
    const size_t base = (size_t)(b * NHEADS + h) * NTOK;

    for (int e = tid; e < 79 * 16; e += 160) {
        int rr = e >> 4, d = e & 15;
        rwT[d][rr] = relw[e];
        rhT[d][rr] = relh[e];
    }
    for (int e = tid; e < 640; e += 160) {
        ((float*)Vc)[e] = g_Vc40[bh * 640 + e];
        ((float*)Vr)[e] = g_Vr40[bh * 640 + e];
    }

    const int qi0 = qc * 320 + tid;
    const int qi1 = qi0 + 160;
    const int r0 = qi0 / 40, c0 = qi0 - r0 * 40;
    const int r1 = qi1 / 40, c1 = qi1 - r1 * 40;
    float q0[16], q1[16];
    load16(&g_Q[(base + (bi * 40 + r0) * WW + bj * 40 + c0) * HD], q0);
    load16(&g_Q[(base + (bi * 40 + r1) * WW + bj * 40 + c1) * HD], q1);
    float o0[16], o1[16];
#pragma unroll
    for (int d = 0; d < 16; d++) { o0[d] = 0.f; o1[d] = 0.f; }
    float ssum0 = 0.f, ssum1 = 0.f;

    for (int t = 0; t < 10; t++) {
        __syncthreads();
#pragma unroll
        for (int l = 0; l < 4; l++) {
            int e = tid + l * 160;
            int key = e >> 2, part = (e & 3) << 2;
            int kidx = t * 160 + key;
            int kr = kidx / 40, kc = kidx - kr * 40;
            int ktok = (bi * 40 + kr) * WW + bj * 40 + kc;
            *(float4*)&Ks[key][part] = *(const float4*)&g_K[(base + ktok) * HD + part];
            *(float4*)&Vs[key][part] = *(const float4*)&g_V[(base + ktok) * HD + part];
        }
        __syncthreads();
#pragma unroll 2
        for (int kk = 0; kk < 160; kk++) {
            float kv[16];
            load16(&Ks[kk][0], kv);
            float s0 = 0.f, s1 = 0.f;
#pragma unroll
            for (int d = 0; d < 16; d++) {
                s0 = fmaf(q0[d], kv[d], s0);
                s1 = fmaf(q1[d], kv[d], s1);
            }
            float ew0 = __expf(s0 * ATTN_SCALE);
            float ew1 = __expf(s1 * ATTN_SCALE);
            ssum0 += ew0; ssum1 += ew1;
            float vv[16];
            load16(&Vs[kk][0], vv);
#pragma unroll
            for (int d = 0; d < 16; d++) {
                o0[d] = fmaf(ew0, vv[d], o0[d]);
                o1[d] = fmaf(ew1, vv[d], o1[d]);
            }
        }
    }
    float inv0 = 1.f / ssum0, inv1 = 1.f / ssum1;
#pragma unroll
    for (int d = 0; d < 16; d++) { o0[d] *= inv0; o1[d] *= inv1; }

    // rel-pos epilogue per query (40 keys each — minor cost)
    {
        const int cw = 39 - c0, rw = 39 - r0;
#pragma unroll 2
        for (int kc = 0; kc < 40; kc++) {
            float w = 0.f, wh = 0.f;
#pragma unroll
            for (int d = 0; d < 16; d++) {
                w = fmaf(q0[d], rwT[d][kc + cw], w);
                wh = fmaf(q0[d], rhT[d][kc + rw], wh);
            }
            float vcv[16], vrv[16];
            load16(&Vc[kc][0], vcv);
            load16(&Vr[kc][0], vrv);
#pragma unroll
            for (int d = 0; d < 16; d++) {
                o0[d] = fmaf(w, vcv[d], o0[d]);
                o0[d] = fmaf(wh, vrv[d], o0[d]);
            }
        }
    }
    {
        const int cw = 39 - c1, rw = 39 - r1;
#pragma unroll 2
        for (int kc = 0; kc < 40; kc++) {
            float w = 0.f, wh = 0.f;
#pragma unroll
            for (int d = 0; d < 16; d++) {
                w = fmaf(q1[d], rwT[d][kc + cw], w);
                wh = fmaf(q1[d], rhT[d][kc + rw], wh);
            }
            float vcv[16], vrv[16];
            load16(&Vc[kc][0], vcv);
            load16(&Vr[kc][0], vrv);
#pragma unroll
            for (int d = 0; d < 16; d++) {
                o1[d] = fmaf(w, vcv[d], o1[d]);
                o1[d] = fmaf(wh, vrv[d], o1[d]);
            }
        }
    }
    // patch-major destination: (bi*2 + bj)*1600 + qi
    const int pbase = (bi * 2 + bj) * 1600;
    float* dst0 = g_Osum + ((size_t)b * NTOK + pbase + qi0) * 128 + h * HD;
    float* dst1 = g_Osum + ((size_t)b * NTOK + pbase + qi1) * 128 + h * HD;
#pragma unroll
    for (int d4 = 0; d4 < 4; d4++) {
        float4 cur = *(float4*)&dst0[4 * d4];
        cur.x += o0[4 * d4 + 0]; cur.y += o0[4 * d4 + 1];
        cur.z += o0[4 * d4 + 2]; cur.w += o0[4 * d4 + 3];
        *(float4*)&dst0[4 * d4] = cur;
    }
#pragma unroll
    for (int d4 = 0; d4 < 4; d4++) {
        float4 cur = *(float4*)&dst1[4 * d4];
        cur.x += o1[4 * d4 + 0]; cur.y += o1[4 * d4 + 1];
        cur.z += o1[4 * d4 + 2]; cur.w += o1[4 * d4 + 3];
        *(float4*)&dst1[4 * d4] = cur;
    }
}

// ---------------- final: out = Osum @ Wc + bc ----------------
__global__ __launch_bounds__(256) void final_gemm_kernel(float* __restrict__ out) {
    __shared__ float As[16][64];
    __shared__ float Bs[16][64];
    const int m0 = blockIdx.x * 64;
    const int n0 = blockIdx.y * 64;
    const int tid = threadIdx.x;
    const int tm = tid >> 4, tn = tid & 15;
    float acc[4][4];
#pragma unroll
    for (int i = 0; i < 4; i++)
#pragma unroll
        for (int j = 0; j < 4; j++) acc[i][j] = 0.f;

    for (int k0 = 0; k0 < 128; k0 += 16) {
        {
            int row = tid >> 2, kp = (tid & 3) << 2;
            float4 av = *(const float4*)&g_Osum[(size_t)(m0 + row) * 128 + k0 + kp];
            As[kp + 0][row] = av.x; As[kp + 1][row] = av.y;
            As[kp + 2][row] = av.z; As[kp + 3][row] = av.w;
            int kk = tid >> 4, j4 = (tid & 15) << 2;
            *(float4*)&Bs[kk][j4] = *(const float4*)&g_Wc[(size_t)(k0 + kk) * 128 + n0 + j4];
        }
        __syncthreads();
#pragma unroll
        for (int kk = 0; kk < 16; kk++) {
            float4 a = *(const float4*)&As[kk][tm << 2];
            float4 bv = *(const float4*)&Bs[kk][tn << 2];
            float aa[4] = {a.x, a.y, a.z, a.w};
            float bb[4] = {bv.x, bv.y, bv.z, bv.w};
#pragma unroll
            for (int i = 0; i < 4; i++)
#pragma unroll
                for (int j = 0; j < 4; j++) acc[i][j] = fmaf(aa[i], bb[j], acc[i][j]);
        }
        __syncthreads();
    }
    float4 bcv = *(const float4*)&g_bc[n0 + (tn << 2)];
    float bb[4] = {bcv.x, bcv.y, bcv.z, bcv.w};
#pragma unroll
    for (int i = 0; i < 4; i++) {
        int t = m0 + (tm << 2) + i;
        float4 v = make_float4(acc[i][0] + bb[0], acc[i][1] + bb[1],
                               acc[i][2] + bb[2], acc[i][3] + bb[3]);
        *(float4*)&out[(size_t)t * 128 + n0 + (tn << 2)] = v;
    }
}

// ---------------- launcher ----------------
extern "C" void kernel_launch(void* const* d_in, const int* in_sizes, int n_in,
                              void* d_out, int out_size) {
    (void)in_sizes; (void)n_in; (void)out_size;
    const float* x      = (const float*)d_in[0];
    const float* wq     = (const float*)d_in[1];
    const float* wkv    = (const float*)d_in[2];
    const float* wproj  = (const float*)d_in[3];
    const float* bproj  = (const float*)d_in[4];
    const float* wfinal = (const float*)d_in[5];
    const float* bfinal = (const float*)d_in[6];
    const float* rw0 = (const float*)d_in[7];
    const float* rh0 = (const float*)d_in[8];
    const float* rw1 = (const float*)d_in[9];
    const float* rh1 = (const float*)d_in[10];
    const float* rw2 = (const float*)d_in[11];
    const float* rh2 = (const float*)d_in[12];
    float* out = (float*)d_out;

    qkv_gemm_kernel<<<dim3(200, 6), 256>>>(x, wq, wkv);
    wc_kernel<<<128, 128>>>(wproj, wfinal, bproj, bfinal);
    vsum40_kernel<<<64, 640>>>();
    // p=4 STORES (initializes g_Osum: every (token,head) covered exactly once)
    attn_small_kernel<4, 8, false><<<800, 128>>>(rw0, rh0);
    attn_small_kernel<8, 2, true><<<800, 128>>>(rw1, rh1);
    attn40_kernel<<<320, 160>>>(rw2, rh2);
    final_gemm_kernel<<<dim3(200, 2), 256>>>(out);
}